// round 1
// baseline (speedup 1.0000x reference)
#include <cuda_runtime.h>

// Problem constants
#define NHEAD   8
#define DK      64
#define LEN     100
#define BS      32
#define DMODEL  512
#define TEMP    20.0f

// Scratch: projected (then normalized in-place) Q and K, flat [32, 100, 512]
__device__ float g_Pq[BS * LEN * DMODEL];
__device__ float g_Pk[BS * LEN * DMODEL];

// ---------------------------------------------------------------------------
// Kernel 1: projection GEMM. P[r][c] = sum_j x[r][j] * w[c][j]
// M=3200, N=512, K=512. Tiles: 64x64 block, BK=16, 256 threads, 4x4/thread.
// grid = (8, 50, 2): z=0 -> q@w_qs^T -> g_Pq ; z=1 -> k@w_ks^T -> g_Pk
// ---------------------------------------------------------------------------
__global__ __launch_bounds__(256) void proj_kernel(
    const float* __restrict__ q, const float* __restrict__ k,
    const float* __restrict__ w_qs, const float* __restrict__ w_ks)
{
    const float* x; const float* w; float* P;
    if (blockIdx.z == 0) { x = q; w = w_qs; P = g_Pq; }
    else                 { x = k; w = w_ks; P = g_Pk; }

    __shared__ float As[16 * 68];   // As[k][m], stride 68 (16B-aligned rows)
    __shared__ float Bs[16 * 68];   // Bs[k][n]

    const int tid = threadIdx.x;
    const int tx = tid & 15, ty = tid >> 4;
    const int row0 = blockIdx.y * 64, col0 = blockIdx.x * 64;

    const int lr = tid >> 2;          // 0..63 (row within tile)
    const int lk = (tid & 3) * 4;     // 0,4,8,12 (k within tile)

    float acc[4][4] = {};

    for (int k0 = 0; k0 < DMODEL; k0 += 16) {
        float4 a = *(const float4*)(x + (size_t)(row0 + lr) * DMODEL + k0 + lk);
        float4 b = *(const float4*)(w + (size_t)(col0 + lr) * DMODEL + k0 + lk);
        As[(lk + 0) * 68 + lr] = a.x; As[(lk + 1) * 68 + lr] = a.y;
        As[(lk + 2) * 68 + lr] = a.z; As[(lk + 3) * 68 + lr] = a.w;
        Bs[(lk + 0) * 68 + lr] = b.x; Bs[(lk + 1) * 68 + lr] = b.y;
        Bs[(lk + 2) * 68 + lr] = b.z; Bs[(lk + 3) * 68 + lr] = b.w;
        __syncthreads();
        #pragma unroll
        for (int kk = 0; kk < 16; kk++) {
            float4 av = *(const float4*)(As + kk * 68 + ty * 4);
            float4 bv = *(const float4*)(Bs + kk * 68 + tx * 4);
            float aa[4] = {av.x, av.y, av.z, av.w};
            float bb[4] = {bv.x, bv.y, bv.z, bv.w};
            #pragma unroll
            for (int i = 0; i < 4; i++)
                #pragma unroll
                for (int j = 0; j < 4; j++)
                    acc[i][j] += aa[i] * bb[j];
        }
        __syncthreads();
    }

    #pragma unroll
    for (int i = 0; i < 4; i++) {
        float4 o = make_float4(acc[i][0], acc[i][1], acc[i][2], acc[i][3]);
        *(float4*)(P + (size_t)(row0 + ty * 4 + i) * DMODEL + col0 + tx * 4) = o;
    }
}

// ---------------------------------------------------------------------------
// Kernel 2: L2-normalize every contiguous 64-float chunk of g_Pq / g_Pk.
// 2 * 32 * 800 = 51200 chunks. One warp per chunk. grid=6400, block=256.
// ---------------------------------------------------------------------------
__global__ __launch_bounds__(256) void norm_kernel()
{
    const int warp = (blockIdx.x * 256 + threadIdx.x) >> 5;   // 0..51199
    const int lane = threadIdx.x & 31;
    float* base = (warp < 25600) ? (g_Pq + (size_t)warp * 64)
                                 : (g_Pk + (size_t)(warp - 25600) * 64);
    float2 v = ((float2*)base)[lane];
    float ss = v.x * v.x + v.y * v.y;
    #pragma unroll
    for (int off = 16; off; off >>= 1)
        ss += __shfl_xor_sync(0xffffffffu, ss, off);
    float inv = 1.0f / fmaxf(sqrtf(ss), 1e-12f);
    ((float2*)base)[lane] = make_float2(v.x * inv, v.y * inv);
}

// ---------------------------------------------------------------------------
// Kernel 3: attention per (qb, kb, h). grid=8192, block=256 (16x16 threads).
// S = Qn Kn^T (100x100, padded to 112x112 register tiles, 7x7 per thread),
// P = exp(20*relu(S)) (no max-subtraction needed: logits in [0,20]),
// O = (P V) / rowsum.
// ---------------------------------------------------------------------------
#define QK_STRIDE 65     // 65 % 32 == 1 -> conflict-free column reads
#define S_STRIDE  104
#define SM_QS     0
#define SM_KS     (112 * QK_STRIDE)
#define SM_VS     (2 * 112 * QK_STRIDE)
#define SM_S      (SM_VS + LEN * 64)
#define SM_RS     (SM_S + 112 * S_STRIDE)
#define SM_FLOATS (SM_RS + 112)
#define SMEM_BYTES (SM_FLOATS * 4)

__global__ __launch_bounds__(256) void attn_kernel(
    const float* __restrict__ v, float* __restrict__ out)
{
    extern __shared__ float sm[];
    float* Qs     = sm + SM_QS;
    float* Ks     = sm + SM_KS;
    float* Vs     = sm + SM_VS;
    float* S      = sm + SM_S;
    float* rowsum = sm + SM_RS;

    const int bx = blockIdx.x;
    const int h  = bx & 7;
    const int qb = (bx >> 3) & 31;
    const int kb = bx >> 8;
    const int tid = threadIdx.x;

    const float* qptr = g_Pq + (size_t)qb * 51200 + h * 6400;
    const float* kptr = g_Pk + (size_t)kb * 51200 + h * 6400;
    const float* vptr = v    + (size_t)kb * 51200 + h * 6400;

    // Stage A: load tiles. Q/K go in with stride 65 (scalar scatter),
    // V stays stride 64 for LDS.128 in stage C.
    for (int i = tid; i < LEN * 16; i += 256) {     // 1600 float4s per tensor
        const int l = i >> 4;
        const int c = (i & 15) << 2;
        float4 a = ((const float4*)qptr)[i];
        float4 b = ((const float4*)kptr)[i];
        Qs[l * QK_STRIDE + c + 0] = a.x; Qs[l * QK_STRIDE + c + 1] = a.y;
        Qs[l * QK_STRIDE + c + 2] = a.z; Qs[l * QK_STRIDE + c + 3] = a.w;
        Ks[l * QK_STRIDE + c + 0] = b.x; Ks[l * QK_STRIDE + c + 1] = b.y;
        Ks[l * QK_STRIDE + c + 2] = b.z; Ks[l * QK_STRIDE + c + 3] = b.w;
        ((float4*)Vs)[i] = ((const float4*)vptr)[i];
    }
    // Zero-pad rows 100..111 of Q and K so the 112-wide compute needs no masks.
    for (int i = tid; i < 12 * QK_STRIDE; i += 256) {
        Qs[LEN * QK_STRIDE + i] = 0.0f;
        Ks[LEN * QK_STRIDE + i] = 0.0f;
    }
    __syncthreads();

    const int tx = tid & 15, ty = tid >> 4;

    // Stage B: S tile, 7x7 registers per thread
    float acc[7][7] = {};
    const float* qrow = Qs + ty * 7 * QK_STRIDE;
    const float* krow = Ks + tx * 7 * QK_STRIDE;
    #pragma unroll 4
    for (int kk = 0; kk < DK; kk++) {
        float a[7], b[7];
        #pragma unroll
        for (int i = 0; i < 7; i++) a[i] = qrow[i * QK_STRIDE + kk];
        #pragma unroll
        for (int j = 0; j < 7; j++) b[j] = krow[j * QK_STRIDE + kk];
        #pragma unroll
        for (int i = 0; i < 7; i++)
            #pragma unroll
            for (int j = 0; j < 7; j++)
                acc[i][j] += a[i] * b[j];
    }

    // exp(20*relu(.)) ; store to S ; accumulate row sums
    float rs[7];
    #pragma unroll
    for (int i = 0; i < 7; i++) rs[i] = 0.0f;
    #pragma unroll
    for (int i = 0; i < 7; i++) {
        const int l = ty * 7 + i;
        #pragma unroll
        for (int j = 0; j < 7; j++) {
            const int m = tx * 7 + j;
            float e = __expf(TEMP * fmaxf(acc[i][j], 0.0f));
            if (m < LEN) {             // padded l-rows give e=exp(0)=1, harmless
                S[l * S_STRIDE + m] = e;
                rs[i] += e;
            }
        }
    }
    // Reduce row sums across the 16 lanes sharing ty (width-16 shuffle).
    #pragma unroll
    for (int off = 8; off; off >>= 1)
        #pragma unroll
        for (int i = 0; i < 7; i++)
            rs[i] += __shfl_down_sync(0xffffffffu, rs[i], off, 16);
    if (tx == 0) {
        #pragma unroll
        for (int i = 0; i < 7; i++) rowsum[ty * 7 + i] = rs[i];
    }
    __syncthreads();

    // Stage C: O = P V  (rows 7 per thread, 4 output cols via float4 V loads)
    float4 o[7];
    #pragma unroll
    for (int i = 0; i < 7; i++) o[i] = make_float4(0.f, 0.f, 0.f, 0.f);
    const float* srow = S + ty * 7 * S_STRIDE;
    #pragma unroll 2
    for (int m = 0; m < LEN; m++) {
        float4 vv = *(const float4*)(Vs + m * 64 + tx * 4);
        #pragma unroll
        for (int i = 0; i < 7; i++) {
            float p = srow[i * S_STRIDE + m];
            o[i].x += p * vv.x; o[i].y += p * vv.y;
            o[i].z += p * vv.z; o[i].w += p * vv.w;
        }
    }

    // Write: out[kb][qb][l][h*64 + d]
    const size_t obase = ((size_t)(kb * 32 + qb) * LEN) * DMODEL + h * 64 + tx * 4;
    #pragma unroll
    for (int i = 0; i < 7; i++) {
        const int l = ty * 7 + i;
        if (l < LEN) {
            float inv = 1.0f / rowsum[l];
            float4 r = make_float4(o[i].x * inv, o[i].y * inv,
                                   o[i].z * inv, o[i].w * inv);
            *(float4*)(out + obase + (size_t)l * DMODEL) = r;
        }
    }
}

// ---------------------------------------------------------------------------
extern "C" void kernel_launch(void* const* d_in, const int* in_sizes, int n_in,
                              void* d_out, int out_size)
{
    const float* q    = (const float*)d_in[0];
    const float* k    = (const float*)d_in[1];
    const float* v    = (const float*)d_in[2];
    const float* w_qs = (const float*)d_in[3];
    const float* w_ks = (const float*)d_in[4];
    float* out = (float*)d_out;

    dim3 gp(8, 50, 2);
    proj_kernel<<<gp, 256>>>(q, k, w_qs, w_ks);
    norm_kernel<<<6400, 256>>>();

    cudaFuncSetAttribute(attn_kernel,
                         cudaFuncAttributeMaxDynamicSharedMemorySize, SMEM_BYTES);
    attn_kernel<<<8192, 256, SMEM_BYTES>>>(v, out);
}

// round 2
// speedup vs baseline: 2.1797x; 2.1797x over previous
#include <cuda_runtime.h>
#include <cuda_bf16.h>
#include <cstdint>

// Problem constants
#define NHEAD   8
#define DK      64
#define LEN     100
#define BS      32
#define DMODEL  512
#define TEMP    20.0f

// Scratch: projected (then normalized in-place) Q and K, flat [32, 100, 512]
__device__ float g_Pq[BS * LEN * DMODEL];
__device__ float g_Pk[BS * LEN * DMODEL];

// ---------------------------------------------------------------------------
// Kernel 1: projection GEMM (unchanged from round 1, 109us)
// ---------------------------------------------------------------------------
__global__ __launch_bounds__(256) void proj_kernel(
    const float* __restrict__ q, const float* __restrict__ k,
    const float* __restrict__ w_qs, const float* __restrict__ w_ks)
{
    const float* x; const float* w; float* P;
    if (blockIdx.z == 0) { x = q; w = w_qs; P = g_Pq; }
    else                 { x = k; w = w_ks; P = g_Pk; }

    __shared__ float As[16 * 68];
    __shared__ float Bs[16 * 68];

    const int tid = threadIdx.x;
    const int tx = tid & 15, ty = tid >> 4;
    const int row0 = blockIdx.y * 64, col0 = blockIdx.x * 64;
    const int lr = tid >> 2;
    const int lk = (tid & 3) * 4;

    float acc[4][4] = {};

    for (int k0 = 0; k0 < DMODEL; k0 += 16) {
        float4 a = *(const float4*)(x + (size_t)(row0 + lr) * DMODEL + k0 + lk);
        float4 b = *(const float4*)(w + (size_t)(col0 + lr) * DMODEL + k0 + lk);
        As[(lk + 0) * 68 + lr] = a.x; As[(lk + 1) * 68 + lr] = a.y;
        As[(lk + 2) * 68 + lr] = a.z; As[(lk + 3) * 68 + lr] = a.w;
        Bs[(lk + 0) * 68 + lr] = b.x; Bs[(lk + 1) * 68 + lr] = b.y;
        Bs[(lk + 2) * 68 + lr] = b.z; Bs[(lk + 3) * 68 + lr] = b.w;
        __syncthreads();
        #pragma unroll
        for (int kk = 0; kk < 16; kk++) {
            float4 av = *(const float4*)(As + kk * 68 + ty * 4);
            float4 bv = *(const float4*)(Bs + kk * 68 + tx * 4);
            float aa[4] = {av.x, av.y, av.z, av.w};
            float bb[4] = {bv.x, bv.y, bv.z, bv.w};
            #pragma unroll
            for (int i = 0; i < 4; i++)
                #pragma unroll
                for (int j = 0; j < 4; j++)
                    acc[i][j] += aa[i] * bb[j];
        }
        __syncthreads();
    }

    #pragma unroll
    for (int i = 0; i < 4; i++) {
        float4 o = make_float4(acc[i][0], acc[i][1], acc[i][2], acc[i][3]);
        *(float4*)(P + (size_t)(row0 + ty * 4 + i) * DMODEL + col0 + tx * 4) = o;
    }
}

// ---------------------------------------------------------------------------
// Kernel 2: L2-normalize every contiguous 64-float chunk (unchanged)
// ---------------------------------------------------------------------------
__global__ __launch_bounds__(256) void norm_kernel()
{
    const int warp = (blockIdx.x * 256 + threadIdx.x) >> 5;
    const int lane = threadIdx.x & 31;
    float* base = (warp < 25600) ? (g_Pq + (size_t)warp * 64)
                                 : (g_Pk + (size_t)(warp - 25600) * 64);
    float2 v = ((float2*)base)[lane];
    float ss = v.x * v.x + v.y * v.y;
    #pragma unroll
    for (int off = 16; off; off >>= 1)
        ss += __shfl_xor_sync(0xffffffffu, ss, off);
    float inv = 1.0f / fmaxf(sqrtf(ss), 1e-12f);
    ((float2*)base)[lane] = make_float2(v.x * inv, v.y * inv);
}

// ---------------------------------------------------------------------------
// Kernel 3: tensor-core attention. One block per (qb, kb, h), 8 warps.
// bf16 hi/lo split (3-mma) for both GEMMs -> near-fp32 accuracy.
//   S[128x112] = Q[128x64] K^T        (warps 4M x 2N, m16n8k16)
//   P = exp(20*relu(S)) masked, bf16 hi/lo, overlaid on Q/K smem
//   O[128x64]  = P[128x112] V
// Smem strides chosen for conflict-free fragment LDS.
// ---------------------------------------------------------------------------
#define QK_ST   72      // bf16 elems per row (36 words): 4g+t conflict-free
#define P_ST    120     // (60 words): 28g+t conflict-free
#define VT_ST   114     // (57 words): transpose-writes conflict-free

#define OFF_QHI  0
#define OFF_QLO  (OFF_QHI + 128 * QK_ST * 2)          // 18432
#define OFF_KHI  (OFF_QLO + 128 * QK_ST * 2)          // 36864
#define OFF_KLO  (OFF_KHI + 112 * QK_ST * 2)          // 52992, end 69120
#define OFF_PHI  0                                     // overlays Q/K
#define OFF_PLO  (OFF_PHI + 128 * P_ST * 2)           // 30720, end 61440 < 69120
#define OFF_VTHI (OFF_KLO + 112 * QK_ST * 2)          // 69120
#define OFF_VTLO (OFF_VTHI + 64 * VT_ST * 2)          // 83712
#define OFF_RS   (OFF_VTLO + 64 * VT_ST * 2)          // 98304
#define ATTN_SMEM (OFF_RS + 128 * 2 * 4)              // 99328 bytes -> 2 CTAs/SM

__device__ __forceinline__ void mma_bf16(float c[4],
    uint32_t a0, uint32_t a1, uint32_t a2, uint32_t a3,
    uint32_t b0, uint32_t b1)
{
    asm volatile(
        "mma.sync.aligned.m16n8k16.row.col.f32.bf16.bf16.f32 "
        "{%0,%1,%2,%3}, {%4,%5,%6,%7}, {%8,%9}, {%0,%1,%2,%3};"
        : "+f"(c[0]), "+f"(c[1]), "+f"(c[2]), "+f"(c[3])
        : "r"(a0), "r"(a1), "r"(a2), "r"(a3), "r"(b0), "r"(b1));
}

__device__ __forceinline__ void split2(float x0, float x1,
                                       uint32_t& hi, uint32_t& lo)
{
    __nv_bfloat16 h0 = __float2bfloat16(x0);
    __nv_bfloat16 h1 = __float2bfloat16(x1);
    float l0 = x0 - __bfloat162float(h0);
    float l1 = x1 - __bfloat162float(h1);
    __nv_bfloat162 hv; hv.x = h0; hv.y = h1;
    __nv_bfloat162 lv = __floats2bfloat162_rn(l0, l1);
    hi = *(uint32_t*)&hv;
    lo = *(uint32_t*)&lv;
}

__global__ __launch_bounds__(256, 2) void attn_kernel(
    const float* __restrict__ v, float* __restrict__ out)
{
    extern __shared__ char sm[];
    uint32_t* QHI = (uint32_t*)(sm + OFF_QHI);
    uint32_t* QLO = (uint32_t*)(sm + OFF_QLO);
    uint32_t* KHI = (uint32_t*)(sm + OFF_KHI);
    uint32_t* KLO = (uint32_t*)(sm + OFF_KLO);
    uint32_t* PHI = (uint32_t*)(sm + OFF_PHI);
    uint32_t* PLO = (uint32_t*)(sm + OFF_PLO);
    uint32_t* VTHI = (uint32_t*)(sm + OFF_VTHI);
    uint32_t* VTLO = (uint32_t*)(sm + OFF_VTLO);
    __nv_bfloat16* VTHI16 = (__nv_bfloat16*)(sm + OFF_VTHI);
    __nv_bfloat16* VTLO16 = (__nv_bfloat16*)(sm + OFF_VTLO);
    float* RS = (float*)(sm + OFF_RS);

    const int bx = blockIdx.x;
    const int h  = bx & 7;
    const int qb = (bx >> 3) & 31;
    const int kb = bx >> 8;
    const int tid = threadIdx.x;

    const float* qptr = g_Pq + (size_t)qb * 51200 + h * 6400;
    const float* kptr = g_Pk + (size_t)kb * 51200 + h * 6400;
    const float* vptr = v    + (size_t)kb * 51200 + h * 6400;

    // ---- Stage Q, K as bf16 hi/lo (rows 0..99; rows >=100 uninit, masked out)
    for (int i = tid; i < LEN * 16; i += 256) {
        const int r = i >> 4;
        const int cw = (i & 15) * 2;             // word offset within row
        float4 a = ((const float4*)qptr)[i];
        uint32_t h0, l0, h1, l1;
        split2(a.x, a.y, h0, l0); split2(a.z, a.w, h1, l1);
        QHI[r * 36 + cw] = h0; QHI[r * 36 + cw + 1] = h1;
        QLO[r * 36 + cw] = l0; QLO[r * 36 + cw + 1] = l1;
        float4 b = ((const float4*)kptr)[i];
        split2(b.x, b.y, h0, l0); split2(b.z, b.w, h1, l1);
        KHI[r * 36 + cw] = h0; KHI[r * 36 + cw + 1] = h1;
        KLO[r * 36 + cw] = l0; KLO[r * 36 + cw + 1] = l1;
    }
    // ---- Transpose V -> Vt[d][m], bf16 hi/lo, keys 100..111 zeroed
    for (int e = tid; e < 64 * 112; e += 256) {
        const int d = e & 63, m = e >> 6;
        float x = (m < LEN) ? vptr[m * 64 + d] : 0.0f;
        __nv_bfloat16 hh = __float2bfloat16(x);
        VTHI16[d * VT_ST + m] = hh;
        VTLO16[d * VT_ST + m] = __float2bfloat16(x - __bfloat162float(hh));
    }
    __syncthreads();

    const int lane = tid & 31, warp = tid >> 5;
    const int g = lane >> 2, t = lane & 3;
    const int wm = warp & 3, wn = warp >> 2;
    const int r0 = wm * 32;

    // ---- S = Q K^T : warp computes rows [r0, r0+32) x cols [56wn, 56wn+56)
    float acc[2][7][4] = {};
    {
        const int c0 = wn * 56;
        #pragma unroll
        for (int ks = 0; ks < 4; ks++) {
            uint32_t ah[2][4], al[2][4];
            #pragma unroll
            for (int i = 0; i < 2; i++) {
                const int rb = (r0 + 16 * i + g) * 36 + ks * 8 + t;
                ah[i][0] = QHI[rb];        al[i][0] = QLO[rb];
                ah[i][1] = QHI[rb + 288];  al[i][1] = QLO[rb + 288];
                ah[i][2] = QHI[rb + 4];    al[i][2] = QLO[rb + 4];
                ah[i][3] = QHI[rb + 292];  al[i][3] = QLO[rb + 292];
            }
            #pragma unroll
            for (int j = 0; j < 7; j++) {
                const int nb = (c0 + 8 * j + g) * 36 + ks * 8 + t;
                uint32_t bh0 = KHI[nb], bh1 = KHI[nb + 4];
                uint32_t bl0 = KLO[nb], bl1 = KLO[nb + 4];
                #pragma unroll
                for (int i = 0; i < 2; i++) {
                    mma_bf16(acc[i][j], ah[i][0], ah[i][1], ah[i][2], ah[i][3], bh0, bh1);
                    mma_bf16(acc[i][j], ah[i][0], ah[i][1], ah[i][2], ah[i][3], bl0, bl1);
                    mma_bf16(acc[i][j], al[i][0], al[i][1], al[i][2], al[i][3], bh0, bh1);
                }
            }
        }
    }
    __syncthreads();   // all Q/K reads done before P overlays them

    // ---- Epilogue: P = exp(20*relu(S)), mask cols>=100, row sums, store hi/lo
    {
        const int c0 = wn * 56;
        float rsum[2][2] = {{0.f, 0.f}, {0.f, 0.f}};
        #pragma unroll
        for (int i = 0; i < 2; i++) {
            #pragma unroll
            for (int j = 0; j < 7; j++) {
                const int c = c0 + 8 * j + 2 * t;
                float e0 = __expf(TEMP * fmaxf(acc[i][j][0], 0.f));
                float e1 = __expf(TEMP * fmaxf(acc[i][j][1], 0.f));
                float e2 = __expf(TEMP * fmaxf(acc[i][j][2], 0.f));
                float e3 = __expf(TEMP * fmaxf(acc[i][j][3], 0.f));
                if (c     >= LEN) { e0 = 0.f; e2 = 0.f; }
                if (c + 1 >= LEN) { e1 = 0.f; e3 = 0.f; }
                rsum[i][0] += e0 + e1;
                rsum[i][1] += e2 + e3;
                const int w0 = (r0 + 16 * i + g) * 60 + (c0 + 8 * j) / 2 + t;
                uint32_t ph, pl;
                split2(e0, e1, ph, pl);
                PHI[w0] = ph;       PLO[w0] = pl;
                split2(e2, e3, ph, pl);
                PHI[w0 + 480] = ph; PLO[w0 + 480] = pl;
            }
            rsum[i][0] += __shfl_xor_sync(0xffffffffu, rsum[i][0], 1);
            rsum[i][0] += __shfl_xor_sync(0xffffffffu, rsum[i][0], 2);
            rsum[i][1] += __shfl_xor_sync(0xffffffffu, rsum[i][1], 1);
            rsum[i][1] += __shfl_xor_sync(0xffffffffu, rsum[i][1], 2);
        }
        if (t == 0) {
            #pragma unroll
            for (int i = 0; i < 2; i++) {
                RS[(r0 + 16 * i + g) * 2 + wn]     = rsum[i][0];
                RS[(r0 + 16 * i + g + 8) * 2 + wn] = rsum[i][1];
            }
        }
    }
    __syncthreads();

    // ---- O = P V : warp computes rows [r0, r0+32) x dv cols [32wn, 32wn+32)
    float o[2][4][4] = {};
    {
        const int n0 = wn * 32;
        #pragma unroll
        for (int ks = 0; ks < 7; ks++) {
            uint32_t ah[2][4], al[2][4];
            #pragma unroll
            for (int i = 0; i < 2; i++) {
                const int rb = (r0 + 16 * i + g) * 60 + ks * 8 + t;
                ah[i][0] = PHI[rb];        al[i][0] = PLO[rb];
                ah[i][1] = PHI[rb + 480];  al[i][1] = PLO[rb + 480];
                ah[i][2] = PHI[rb + 4];    al[i][2] = PLO[rb + 4];
                ah[i][3] = PHI[rb + 484];  al[i][3] = PLO[rb + 484];
            }
            #pragma unroll
            for (int j = 0; j < 4; j++) {
                const int nb = (n0 + 8 * j + g) * 57 + ks * 8 + t;
                uint32_t bh0 = VTHI[nb], bh1 = VTHI[nb + 4];
                uint32_t bl0 = VTLO[nb], bl1 = VTLO[nb + 4];
                #pragma unroll
                for (int i = 0; i < 2; i++) {
                    mma_bf16(o[i][j], ah[i][0], ah[i][1], ah[i][2], ah[i][3], bh0, bh1);
                    mma_bf16(o[i][j], ah[i][0], ah[i][1], ah[i][2], ah[i][3], bl0, bl1);
                    mma_bf16(o[i][j], al[i][0], al[i][1], al[i][2], al[i][3], bh0, bh1);
                }
            }
        }
    }

    // ---- Output: divide by rowsum, write [kb][qb][l][h*64+d]
    const size_t ob = ((size_t)(kb * 32 + qb) * LEN) * DMODEL + h * 64;
    #pragma unroll
    for (int i = 0; i < 2; i++) {
        const int r = r0 + 16 * i + g;
        float inv0 = 0.f, inv1 = 0.f;
        if (r < LEN)     inv0 = 1.0f / (RS[r * 2] + RS[r * 2 + 1]);
        if (r + 8 < LEN) inv1 = 1.0f / (RS[(r + 8) * 2] + RS[(r + 8) * 2 + 1]);
        #pragma unroll
        for (int j = 0; j < 4; j++) {
            const int c = wn * 32 + 8 * j + 2 * t;
            if (r < LEN) {
                float2 st = make_float2(o[i][j][0] * inv0, o[i][j][1] * inv0);
                *(float2*)(out + ob + (size_t)r * DMODEL + c) = st;
            }
            if (r + 8 < LEN) {
                float2 st = make_float2(o[i][j][2] * inv1, o[i][j][3] * inv1);
                *(float2*)(out + ob + (size_t)(r + 8) * DMODEL + c) = st;
            }
        }
    }
}

// ---------------------------------------------------------------------------
extern "C" void kernel_launch(void* const* d_in, const int* in_sizes, int n_in,
                              void* d_out, int out_size)
{
    const float* q    = (const float*)d_in[0];
    const float* k    = (const float*)d_in[1];
    const float* v    = (const float*)d_in[2];
    const float* w_qs = (const float*)d_in[3];
    const float* w_ks = (const float*)d_in[4];
    float* out = (float*)d_out;

    dim3 gp(8, 50, 2);
    proj_kernel<<<gp, 256>>>(q, k, w_qs, w_ks);
    norm_kernel<<<6400, 256>>>();

    cudaFuncSetAttribute(attn_kernel,
                         cudaFuncAttributeMaxDynamicSharedMemorySize, ATTN_SMEM);
    attn_kernel<<<8192, 256, ATTN_SMEM>>>(v, out);
}